// round 14
// baseline (speedup 1.0000x reference)
#include <cuda_runtime.h>
#include <cuda_bf16.h>

// Problem constants: B=512, S=32768, alpha=0.1, beta=0.9
#define B_CONST 512
#define S_CONST 32768

// log(0.1), log(0.9). Note log(1-alpha)=log(beta), log(1-beta)=log(alpha).
#define LOG_A   (-2.3025850929940457f)   // log(0.1)
#define LOG_1A  (-0.10536051565782628f)  // log(0.9)
#define LOG_B   (-0.10536051565782628f)  // log(0.9)
#define LOG_1B  (-2.3025850929940457f)   // log(0.1)

constexpr int THREADS = 256;              // 8 warps
constexpr int ITERS   = 8;                // float4-iterations per warp
constexpr int WSEG    = ITERS * 64;       // 512 s-values per warp
constexpr int CHUNK   = (THREADS / 32) * WSEG;   // 4096 s per block
constexpr int BPR     = S_CONST / CHUNK;  // 8 blocks per row
constexpr int GRID    = B_CONST * BPR;    // 4096 blocks
constexpr unsigned FULL = 0xffffffffu;

__device__ float g_partials[GRID];

// KL transition term: prev=(pp0,pp1), curr=(q0,q1); logs precomputed.
__device__ __forceinline__ float div_term_l(float pp0, float pp1,
                                            float q0, float q1,
                                            float l0, float l1)
{
    float t1 = q1 * (l1 - LOG_B)  + q0 * (l0 - LOG_1B);
    float t2 = q1 * (l1 - LOG_1B) + q0 * (l0 - LOG_B);
    return pp1 * t1 + pp0 * t2;
}

__global__ __launch_bounds__(THREADS)
void ekl_main_kernel(const float* __restrict__ post,
                     const int* __restrict__ length)
{
    const int bid  = blockIdx.x;
    const int b    = bid / BPR;
    const int c    = bid % BPR;
    const int len  = length[b];       // 1 <= len <= S (int32)
    const int s0   = c * CHUNK;
    const int lane = threadIdx.x & 31;
    const int warp = threadIdx.x >> 5;

    float sum = 0.0f;

    // Warp-uniform segment: s in [segbase, segbase + WSEG)
    const int segbase = s0 + warp * WSEG;

    if (segbase < len) {
        const float2* row  = reinterpret_cast<const float2*>(post)
                             + (size_t)b * S_CONST;
        const float4* rowq = reinterpret_cast<const float4*>(row);
        const int qbase = (segbase >> 1) + lane;   // this lane's first quad

        // Cross-warp-boundary carry: pair at s = segbase-1 (lane 0 only).
        float cr0 = 0.0f, cr1 = 0.0f;
        if (segbase > 0 && lane == 0) {
            float2 pv = row[segbase - 1];
            cr0 = pv.x; cr1 = pv.y;
        }

        if (segbase > 0 && segbase + WSEG <= len) {
            // ---- FAST PATH (warp-uniform): every transition valid. ----
            float4 V[ITERS];
            #pragma unroll
            for (int i = 0; i < ITERS; ++i)
                V[i] = rowq[qbase + i * 32];

            #pragma unroll
            for (int i = 0; i < ITERS; ++i) {
                float c0a = V[i].x, c1a = V[i].y;   // pair at s
                float c0b = V[i].z, c1b = V[i].w;   // pair at s+1

                float pv0 = __shfl_up_sync(FULL, c0b, 1);
                float pv1 = __shfl_up_sync(FULL, c1b, 1);
                if (lane == 0) { pv0 = cr0; pv1 = cr1; }

                float l0a = __logf(c0a), l1a = __logf(c1a);
                float l0b = __logf(c0b), l1b = __logf(c1b);

                sum += div_term_l(pv0, pv1, c0a, c1a, l0a, l1a);
                sum += div_term_l(c0a, c1a, c0b, c1b, l0b, l1b);

                cr0 = __shfl_sync(FULL, c0b, 31);
                cr1 = __shfl_sync(FULL, c1b, 31);
            }
        } else {
            // ---- SLOW PATH: segment contains s==0 or the len cutoff. ----
            float4 V[ITERS];
            #pragma unroll
            for (int i = 0; i < ITERS; ++i)
                if (segbase + i * 64 < len)
                    V[i] = rowq[qbase + i * 32];

            #pragma unroll
            for (int i = 0; i < ITERS; ++i) {
                if (segbase + i * 64 >= len) break;   // warp-uniform

                float c0a = V[i].x, c1a = V[i].y;
                float c0b = V[i].z, c1b = V[i].w;

                float pv0 = __shfl_up_sync(FULL, c0b, 1);
                float pv1 = __shfl_up_sync(FULL, c1b, 1);
                if (lane == 0) { pv0 = cr0; pv1 = cr1; }

                const int sidx = segbase + i * 64 + 2 * lane;

                float l0a = __logf(c0a), l1a = __logf(c1a);
                float l0b = __logf(c0b), l1b = __logf(c1b);

                if (sidx == 0) {
                    // first-term contribution at s = 0 (len >= 1 always)
                    sum += c1a * (l1a - LOG_A) + c0a * (l0a - LOG_1A);
                } else if (sidx < len) {
                    sum += div_term_l(pv0, pv1, c0a, c1a, l0a, l1a);
                }
                if (sidx + 1 < len)
                    sum += div_term_l(c0a, c1a, c0b, c1b, l0b, l1b);

                cr0 = __shfl_sync(FULL, c0b, 31);
                cr1 = __shfl_sync(FULL, c1b, 31);
            }
        }
    }

    // Deterministic block reduction: warp shuffle tree + smem
    #pragma unroll
    for (int off = 16; off > 0; off >>= 1)
        sum += __shfl_down_sync(FULL, sum, off);

    __shared__ float wsum[THREADS / 32];
    if (lane == 0) wsum[warp] = sum;
    __syncthreads();

    if (warp == 0) {
        float v = (lane < THREADS / 32) ? wsum[lane] : 0.0f;
        #pragma unroll
        for (int off = 4; off > 0; off >>= 1)
            v += __shfl_down_sync(FULL, v, off);
        if (lane == 0) {
            // Release store: pairs with ld.acquire in the final kernel.
            asm volatile("st.release.gpu.global.f32 [%0], %1;"
                         :: "l"(&g_partials[bid]), "f"(v) : "memory");
        }
    }

    // All partial stores issued before any thread triggers.
    __syncthreads();

    // Early PDL trigger: secondary's griddepcontrol.wait releases once ALL
    // CTAs have executed this (i.e., right after the last partial store),
    // skipping the primary's exit/drain/completion-signal latency.
    asm volatile("griddepcontrol.launch_dependents;" ::: "memory");
}

// Final reduction, PDL-overlapped. Acquire loads pair with the primary's
// release stores -> partials visible without relying on kernel completion.
__global__ __launch_bounds__(1024)
void ekl_final_kernel(float* __restrict__ out)
{
    asm volatile("griddepcontrol.wait;" ::: "memory");

    // 4096 partials; 1024 threads x 4 scalar acquire loads, fixed order.
    float s = 0.0f;
    #pragma unroll
    for (int i = 0; i < 4; ++i) {
        float x;
        asm volatile("ld.acquire.gpu.global.f32 %0, [%1];"
                     : "=f"(x)
                     : "l"(&g_partials[threadIdx.x + i * 1024])
                     : "memory");
        s += x;
    }

    #pragma unroll
    for (int off = 16; off > 0; off >>= 1)
        s += __shfl_down_sync(0xffffffffu, s, off);

    __shared__ float wsum[32];
    const int lane = threadIdx.x & 31;
    const int wid  = threadIdx.x >> 5;
    if (lane == 0) wsum[wid] = s;
    __syncthreads();

    if (wid == 0) {
        float v = wsum[lane];   // exactly 32 warps
        #pragma unroll
        for (int off = 16; off > 0; off >>= 1)
            v += __shfl_down_sync(0xffffffffu, v, off);
        if (lane == 0) out[0] = v / (float)B_CONST;
    }
}

extern "C" void kernel_launch(void* const* d_in, const int* in_sizes, int n_in,
                              void* d_out, int out_size)
{
    const float* post = (const float*)d_in[0];   // (B, S, 2) f32 interleaved
    const int*   len  = (const int*)d_in[1];     // (B,) int32 on device
    float*       out  = (float*)d_out;           // scalar f32

    ekl_main_kernel<<<GRID, THREADS>>>(post, len);

    // Secondary with Programmatic Stream Serialization: launches while the
    // primary runs; execution gated by griddepcontrol.wait.
    cudaLaunchConfig_t cfg = {};
    cfg.gridDim  = dim3(1, 1, 1);
    cfg.blockDim = dim3(1024, 1, 1);
    cfg.dynamicSmemBytes = 0;
    cudaLaunchAttribute attrs[1];
    attrs[0].id = cudaLaunchAttributeProgrammaticStreamSerialization;
    attrs[0].val.programmaticStreamSerializationAllowed = 1;
    cfg.attrs    = attrs;
    cfg.numAttrs = 1;
    cudaLaunchKernelEx(&cfg, ekl_final_kernel, (float*)d_out);
}

// round 15
// speedup vs baseline: 1.1199x; 1.1199x over previous
#include <cuda_runtime.h>
#include <cuda_bf16.h>

// Problem constants: B=512, S=32768, alpha=0.1, beta=0.9
#define B_CONST 512
#define S_CONST 32768

// log(0.1), log(0.9). Note log(1-alpha)=log(beta), log(1-beta)=log(alpha).
#define LOG_A   (-2.3025850929940457f)   // log(0.1)
#define LOG_1A  (-0.10536051565782628f)  // log(0.9)
#define LOG_B   (-0.10536051565782628f)  // log(0.9)
#define LOG_1B  (-2.3025850929940457f)   // log(0.1)

constexpr int THREADS = 256;              // 8 warps
constexpr int ITERS   = 8;                // float4-iterations per warp
constexpr int WSEG    = ITERS * 64;       // 512 s-values per warp
constexpr int CHUNK   = (THREADS / 32) * WSEG;   // 4096 s per block
constexpr int BPR     = S_CONST / CHUNK;  // 8 blocks per row
constexpr int GRID    = B_CONST * BPR;    // 4096 blocks
constexpr unsigned FULL = 0xffffffffu;

__device__ float g_partials[GRID];

// KL transition term: prev=(pp0,pp1), curr=(q0,q1); logs precomputed.
__device__ __forceinline__ float div_term_l(float pp0, float pp1,
                                            float q0, float q1,
                                            float l0, float l1)
{
    float t1 = q1 * (l1 - LOG_B)  + q0 * (l0 - LOG_1B);
    float t2 = q1 * (l1 - LOG_1B) + q0 * (l0 - LOG_B);
    return pp1 * t1 + pp0 * t2;
}

__global__ __launch_bounds__(THREADS)
void ekl_main_kernel(const float* __restrict__ post,
                     const int* __restrict__ length)
{
    const int bid  = blockIdx.x;
    // Chunk-major ordering: blocks [0,512) = chunk 0 of every row (always
    // active), blocks [3584,4096) = chunk 7 (mostly masked -> drain fast).
    const int c    = bid >> 9;        // bid / B_CONST
    const int b    = bid & 511;       // bid % B_CONST
    const int len  = length[b];       // 1 <= len <= S (int32)
    const int s0   = c * CHUNK;
    const int lane = threadIdx.x & 31;
    const int warp = threadIdx.x >> 5;

    float sum = 0.0f;

    // Warp-uniform segment: s in [segbase, segbase + WSEG)
    const int segbase = s0 + warp * WSEG;

    if (segbase < len) {
        const float2* row  = reinterpret_cast<const float2*>(post)
                             + (size_t)b * S_CONST;
        const float4* rowq = reinterpret_cast<const float4*>(row);
        const int qbase = (segbase >> 1) + lane;   // this lane's first quad

        // Cross-warp-boundary seed: pair at s = segbase-1 (lane 0 only).
        float sd0 = 0.0f, sd1 = 0.0f;
        if (segbase > 0 && lane == 0) {
            float2 pv = row[segbase - 1];
            sd0 = pv.x; sd1 = pv.y;
        }

        if (segbase > 0 && segbase + WSEG <= len) {
            // ---- FAST PATH (warp-uniform): every transition valid. ----
            float4 V[ITERS];
            #pragma unroll
            for (int i = 0; i < ITERS; ++i)
                V[i] = rowq[qbase + i * 32];

            #pragma unroll
            for (int i = 0; i < ITERS; ++i) {
                float c0a = V[i].x, c1a = V[i].y;   // pair at s
                float c0b = V[i].z, c1b = V[i].w;   // pair at s+1

                // prev for lane>0: neighbor's (z,w). For lane 0: lane 31 of
                // the PREVIOUS quad (independent shuffle, no loop carry).
                float pv0 = __shfl_up_sync(FULL, c0b, 1);
                float pv1 = __shfl_up_sync(FULL, c1b, 1);
                float b0, b1;
                if (i == 0) { b0 = sd0; b1 = sd1; }
                else {
                    b0 = __shfl_sync(FULL, V[i-1].z, 31);
                    b1 = __shfl_sync(FULL, V[i-1].w, 31);
                }
                if (lane == 0) { pv0 = b0; pv1 = b1; }

                float l0a = __logf(c0a), l1a = __logf(c1a);
                float l0b = __logf(c0b), l1b = __logf(c1b);

                sum += div_term_l(pv0, pv1, c0a, c1a, l0a, l1a);
                sum += div_term_l(c0a, c1a, c0b, c1b, l0b, l1b);
            }
        } else {
            // ---- SLOW PATH: segment contains s==0 or the len cutoff. ----
            float4 V[ITERS];
            #pragma unroll
            for (int i = 0; i < ITERS; ++i)
                if (segbase + i * 64 < len)
                    V[i] = rowq[qbase + i * 32];

            float cr0 = sd0, cr1 = sd1;
            #pragma unroll
            for (int i = 0; i < ITERS; ++i) {
                if (segbase + i * 64 >= len) break;   // warp-uniform

                float c0a = V[i].x, c1a = V[i].y;
                float c0b = V[i].z, c1b = V[i].w;

                float pv0 = __shfl_up_sync(FULL, c0b, 1);
                float pv1 = __shfl_up_sync(FULL, c1b, 1);
                if (lane == 0) { pv0 = cr0; pv1 = cr1; }

                const int sidx = segbase + i * 64 + 2 * lane;

                float l0a = __logf(c0a), l1a = __logf(c1a);
                float l0b = __logf(c0b), l1b = __logf(c1b);

                if (sidx == 0) {
                    // first-term contribution at s = 0 (len >= 1 always)
                    sum += c1a * (l1a - LOG_A) + c0a * (l0a - LOG_1A);
                } else if (sidx < len) {
                    sum += div_term_l(pv0, pv1, c0a, c1a, l0a, l1a);
                }
                if (sidx + 1 < len)
                    sum += div_term_l(c0a, c1a, c0b, c1b, l0b, l1b);

                cr0 = __shfl_sync(FULL, c0b, 31);
                cr1 = __shfl_sync(FULL, c1b, 31);
            }
        }
    }

    // Deterministic block reduction: warp shuffle tree + smem
    #pragma unroll
    for (int off = 16; off > 0; off >>= 1)
        sum += __shfl_down_sync(FULL, sum, off);

    __shared__ float wsum[THREADS / 32];
    if (lane == 0) wsum[warp] = sum;
    __syncthreads();

    if (warp == 0) {
        float v = (lane < THREADS / 32) ? wsum[lane] : 0.0f;
        #pragma unroll
        for (int off = 4; off > 0; off >>= 1)
            v += __shfl_down_sync(FULL, v, off);
        if (lane == 0) g_partials[bid] = v;   // plain store (PDL pattern)
    }
    __syncthreads();   // partial store precedes every thread's trigger

    // Canonical PDL trigger: writes before this are visible to the
    // dependent grid after its griddepcontrol.wait.
    asm volatile("griddepcontrol.launch_dependents;" ::: "memory");
}

// Final reduction, PDL-gated; plain batched loads (MLP=4).
__global__ __launch_bounds__(1024)
void ekl_final_kernel(float* __restrict__ out)
{
    asm volatile("griddepcontrol.wait;" ::: "memory");

    const float4* p4 = reinterpret_cast<const float4*>(g_partials);
    float4 a = p4[threadIdx.x];          // 4096 floats = 1024 float4
    float s = (a.x + a.y) + (a.z + a.w);

    #pragma unroll
    for (int off = 16; off > 0; off >>= 1)
        s += __shfl_down_sync(0xffffffffu, s, off);

    __shared__ float wsum[32];
    const int lane = threadIdx.x & 31;
    const int wid  = threadIdx.x >> 5;
    if (lane == 0) wsum[wid] = s;
    __syncthreads();

    if (wid == 0) {
        float v = wsum[lane];   // exactly 32 warps
        #pragma unroll
        for (int off = 16; off > 0; off >>= 1)
            v += __shfl_down_sync(0xffffffffu, v, off);
        if (lane == 0) out[0] = v / (float)B_CONST;
    }
}

extern "C" void kernel_launch(void* const* d_in, const int* in_sizes, int n_in,
                              void* d_out, int out_size)
{
    const float* post = (const float*)d_in[0];   // (B, S, 2) f32 interleaved
    const int*   len  = (const int*)d_in[1];     // (B,) int32 on device
    float*       out  = (float*)d_out;           // scalar f32

    ekl_main_kernel<<<GRID, THREADS>>>(post, len);

    // Secondary with Programmatic Stream Serialization: launches while the
    // primary runs; execution gated by griddepcontrol.wait.
    cudaLaunchConfig_t cfg = {};
    cfg.gridDim  = dim3(1, 1, 1);
    cfg.blockDim = dim3(1024, 1, 1);
    cfg.dynamicSmemBytes = 0;
    cudaLaunchAttribute attrs[1];
    attrs[0].id = cudaLaunchAttributeProgrammaticStreamSerialization;
    attrs[0].val.programmaticStreamSerializationAllowed = 1;
    cfg.attrs    = attrs;
    cfg.numAttrs = 1;
    cudaLaunchKernelEx(&cfg, ekl_final_kernel, (float*)d_out);
}